// round 15
// baseline (speedup 1.0000x reference)
#include <cuda_runtime.h>
#include <cuda_bf16.h>
#include <cuda_fp16.h>
#include <stdint.h>

#define Bb 16
#define Qd 2048
#define Kd 2048
#define Fd 128
#define KT 64
#define NT 256

// kernel1 smem (words): QS[128][68] + KS[64][68]
#define SMEM1_BYTES ((128*68 + 64*68)*4)

#define PACKBF2(r, lo, hi) asm("cvt.rn.bf16x2.f32 %0, %1, %2;" : "=r"(r) : "f"(hi), "f"(lo))
#define EX2(d, x) asm("ex2.approx.f32 %0, %1;" : "=f"(d) : "f"(x))
#define SQRTA(d, x) asm("sqrt.approx.f32 %0, %1;" : "=f"(d) : "f"(x))

__device__ float  g_lsum[Bb * Qd];
__device__ __half g_E[(size_t)256 * 32 * 8192];      // [cta][tile][warp][lane*32 + ..]
__device__ uint4  g_V[(size_t)Bb * 32 * 64 * 32];    // [b][tile][blk=ks*16+jn][lane]

__device__ __forceinline__ void mma16816(float& c0, float& c1, float& c2, float& c3,
                                         uint32_t a0, uint32_t a1, uint32_t a2, uint32_t a3,
                                         uint32_t b0, uint32_t b1) {
    asm volatile("mma.sync.aligned.m16n8k16.row.col.f32.bf16.bf16.f32 "
        "{%0,%1,%2,%3}, {%4,%5,%6,%7}, {%8,%9}, {%0,%1,%2,%3};"
        : "+f"(c0), "+f"(c1), "+f"(c2), "+f"(c3)
        : "r"(a0), "r"(a1), "r"(a2), "r"(a3), "r"(b0), "r"(b1));
}

#define LDSM4(d0, d1, d2, d3, addr) \
    asm volatile("ldmatrix.sync.aligned.m8n8.x4.shared.b16 {%0,%1,%2,%3}, [%4];" \
        : "=r"(d0), "=r"(d1), "=r"(d2), "=r"(d3) : "r"(addr))

extern __shared__ uint32_t smw[];

// ---------------- kernel 0: V -> hi/lo bf16 fragment-order scratch ----------------
__global__ void __launch_bounds__(NT, 2) vprep_kernel(const float* __restrict__ v)
{
    const int t = blockIdx.x, b = blockIdx.y;
    const int tid = threadIdx.x;
    const float* vp = v + ((size_t)b * Kd + t * KT) * Fd;
    uint4* gvt = g_V + ((size_t)(b * 32 + t)) * 2048;

    #pragma unroll
    for (int it = 0; it < 8; it++) {
        int idx = tid + it * NT;            // 0..2047
        int blk = idx >> 5, lane = idx & 31;
        int gid = lane >> 2, tig = lane & 3;
        int row = (blk >> 4) * 16 + tig * 2;
        int col = (blk & 15) * 8 + gid;
        float f0 = vp[row * Fd + col];
        float f1 = vp[(row + 1) * Fd + col];
        float f2 = vp[(row + 8) * Fd + col];
        float f3 = vp[(row + 9) * Fd + col];
        uint32_t pha, phb, pla, plb;
        PACKBF2(pha, f0, f1);
        PACKBF2(phb, f2, f3);
        float r0 = f0 - __uint_as_float(pha << 16);
        float r1 = f1 - __uint_as_float(pha & 0xffff0000u);
        PACKBF2(pla, r0, r1);
        float r2 = f2 - __uint_as_float(phb << 16);
        float r3 = f3 - __uint_as_float(phb & 0xffff0000u);
        PACKBF2(plb, r2, r3);
        gvt[idx] = make_uint4(pha, pla, phb, plb);
    }
}

// ---------------- kernel 1: S = QK^T, E = exp(s/sqrt(128) - 2) -> g_E, row sums -> g_lsum ----------------
__global__ void __launch_bounds__(NT, 1) lsum_kernel(
    const float* __restrict__ q, const float* __restrict__ k)
{
    const int b = blockIdx.y, q0 = blockIdx.x * 128;
    const int cid = b * 16 + blockIdx.x;
    const int tid = threadIdx.x;
    const int wid = tid >> 5, lane = tid & 31;
    const int gid = lane >> 2, tig = lane & 3;

    uint32_t* QS = smw;
    uint32_t* KS = smw + 128 * 68;

    const float C1 = 0.12753859788f;    // log2(e)/sqrt(128)
    const float C0 = -2.88539008178f;   // -2*log2(e)

    {
        const float* qp = q + ((size_t)b * Qd + q0) * Fd;
        #pragma unroll
        for (int it = 0; it < 16; it++) {
            int widx = tid + it * 256;
            int row = widx >> 5, w4 = widx & 31;
            float4 t = *(const float4*)(qp + row * Fd + 4 * w4);
            uint32_t p0, p1;
            PACKBF2(p0, t.x, t.y);
            PACKBF2(p1, t.z, t.w);
            *(uint2*)(QS + row * 68 + 2 * w4) = make_uint2(p0, p1);
        }
    }

    const int lm = lane >> 3, lr = lane & 7;
    const uint32_t qsb = (uint32_t)__cvta_generic_to_shared(QS);
    const uint32_t ksb = (uint32_t)__cvta_generic_to_shared(KS);
    const uint32_t aAddr0 = qsb + (((wid * 16 + ((lm & 1) << 3) + lr) * 68) + ((lm >> 1) << 2)) * 4;
    const uint32_t bAddr0 = ksb + (((((lm >> 1) << 3) + lr) * 68) + ((lm & 1) << 2)) * 4;

    float lsum0 = 0.f, lsum1 = 0.f;

    for (int t = 0; t < 32; t++) {
        const int k0 = t * KT;
        {
            const float* kp = k + ((size_t)b * Kd + k0) * Fd;
            #pragma unroll
            for (int it = 0; it < 8; it++) {
                int widx = tid + it * 256;
                int row = widx >> 5, w4 = widx & 31;
                float4 tt = *(const float4*)(kp + row * Fd + 4 * w4);
                uint32_t p0, p1;
                PACKBF2(p0, tt.x, tt.y);
                PACKBF2(p1, tt.z, tt.w);
                *(uint2*)(KS + row * 68 + 2 * w4) = make_uint2(p0, p1);
            }
        }
        __syncthreads();

        float sc[8][4];
        #pragma unroll
        for (int j = 0; j < 8; j++)
            #pragma unroll
            for (int c = 0; c < 4; c++) sc[j][c] = 0.f;

        #pragma unroll
        for (int ks = 0; ks < 8; ks++) {
            uint32_t a0, a1, a2, a3;
            LDSM4(a0, a1, a2, a3, aAddr0 + ks * 32);
            #pragma unroll
            for (int jp = 0; jp < 4; jp++) {
                uint32_t b0, b1, b2, b3;
                LDSM4(b0, b1, b2, b3, bAddr0 + jp * (16 * 68 * 4) + ks * 32);
                mma16816(sc[2*jp][0], sc[2*jp][1], sc[2*jp][2], sc[2*jp][3],
                         a0, a1, a2, a3, b0, b1);
                mma16816(sc[2*jp+1][0], sc[2*jp+1][1], sc[2*jp+1][2], sc[2*jp+1][3],
                         a0, a1, a2, a3, b2, b3);
            }
        }

        uint32_t Ebuf[16];
        #pragma unroll
        for (int j = 0; j < 8; j++) {
            float e0, e1, e2, e3;
            EX2(e0, fmaf(sc[j][0], C1, C0));
            EX2(e1, fmaf(sc[j][1], C1, C0));
            EX2(e2, fmaf(sc[j][2], C1, C0));
            EX2(e3, fmaf(sc[j][3], C1, C0));
            lsum0 += e0 + e1;
            lsum1 += e2 + e3;
            __half2 hA = __floats2half2_rn(e0, e1);
            __half2 hB = __floats2half2_rn(e2, e3);
            Ebuf[2*j]   = *(uint32_t*)&hA;
            Ebuf[2*j+1] = *(uint32_t*)&hB;
        }
        {
            const size_t eb = (((size_t)cid * 32 + t) * 8 + wid) * 1024 + lane * 32;
            uint4* ep = (uint4*)&g_E[eb];
            const uint4* sp = (const uint4*)Ebuf;
            ep[0] = sp[0]; ep[1] = sp[1]; ep[2] = sp[2]; ep[3] = sp[3];
        }
        __syncthreads();
    }

    lsum0 += __shfl_xor_sync(0xffffffffu, lsum0, 1);
    lsum0 += __shfl_xor_sync(0xffffffffu, lsum0, 2);
    lsum1 += __shfl_xor_sync(0xffffffffu, lsum1, 1);
    lsum1 += __shfl_xor_sync(0xffffffffu, lsum1, 2);
    if (tig == 0) {
        g_lsum[(size_t)b * Qd + q0 + wid * 16 + gid] = lsum0;
        g_lsum[(size_t)b * Qd + q0 + wid * 16 + gid + 8] = lsum1;
    }
}

// ---------------- kernel 2: P = (am?0:E*inv) - (or?0:dist), O = P @ V  (no smem, no barriers) ----------------
__global__ void __launch_bounds__(NT, 2) alibi_main_kernel(
    const float* __restrict__ cq, const float* __restrict__ ck,
    const int* __restrict__ am, const int* __restrict__ alm,
    const float* __restrict__ bias_scale, const float* __restrict__ running_mean,
    float* __restrict__ out)
{
    const int b = blockIdx.y, q0 = blockIdx.x * 128;
    const int cid = b * 16 + blockIdx.x;
    const int tid = threadIdx.x;
    const int wid = tid >> 5, lane = tid & 31;
    const int gid = lane >> 2, tig = lane & 3;

    const float dscale = bias_scale[0] / running_mean[0];

    const int r0l = wid * 16 + gid;
    const size_t r0g = (size_t)b * Qd + q0 + r0l;
    const size_t r1g = r0g + 8;
    const float cqx0 = cq[2 * r0g], cqy0 = cq[2 * r0g + 1];
    const float cqx1 = cq[2 * r1g], cqy1 = cq[2 * r1g + 1];
    const size_t m0 = r0g * (size_t)Kd, m1 = r1g * (size_t)Kd;
    const float inv0 = 1.f / g_lsum[r0g];
    const float inv1 = 1.f / g_lsum[r1g];

    float acc[16][4];
    #pragma unroll
    for (int jn = 0; jn < 16; jn++)
        #pragma unroll
        for (int c = 0; c < 4; c++) acc[jn][c] = 0.f;

    for (int t = 0; t < 32; t++) {
        const int k0 = t * KT;

        // E fragments: 4 x LDG.128
        uint32_t Er[16];
        {
            const size_t eb = (((size_t)cid * 32 + t) * 8 + wid) * 1024 + lane * 32;
            const uint4* ep = (const uint4*)&g_E[eb];
            uint4* dp = (uint4*)Er;
            dp[0] = ep[0]; dp[1] = ep[1]; dp[2] = ep[2]; dp[3] = ep[3];
        }

        const uint4* gvt = g_V + ((size_t)(b * 32 + t)) * 2048 + lane;

        #pragma unroll
        for (int ks = 0; ks < 4; ks++) {
            uint32_t HA0, HA1, HB0, HB1, LA0, LA1, LB0, LB1;
            #pragma unroll
            for (int jj = 0; jj < 2; jj++) {
                int j = 2 * ks + jj;
                int c0 = k0 + j * 8 + tig * 2;
                float4 ckv = *(const float4*)(ck + ((size_t)b * Kd + c0) * 2);
                int2 a0m = *(const int2*)(am  + m0 + c0);
                int2 a1m = *(const int2*)(am  + m1 + c0);
                int2 l0m = *(const int2*)(alm + m0 + c0);
                int2 l1m = *(const int2*)(alm + m1 + c0);

                float2 fA = __half22float2(*(__half2*)&Er[2*j]);
                float2 fB = __half22float2(*(__half2*)&Er[2*j+1]);
                float e00 = fA.x, e01 = fA.y, e10 = fB.x, e11 = fB.y;

                float dxa = cqx0 - ckv.x, dya = cqy0 - ckv.y;
                float dxb = cqx0 - ckv.z, dyb = cqy0 - ckv.w;
                float dxc = cqx1 - ckv.x, dyc = cqy1 - ckv.y;
                float dxd = cqx1 - ckv.z, dyd = cqy1 - ckv.w;
                float d00, d01, d10, d11;
                SQRTA(d00, fmaf(dxa, dxa, dya * dya));
                SQRTA(d01, fmaf(dxb, dxb, dyb * dyb));
                SQRTA(d10, fmaf(dxc, dxc, dyc * dyc));
                SQRTA(d11, fmaf(dxd, dxd, dyd * dyd));

                d00 = (a0m.x | l0m.x) ? 0.f : d00 * dscale;
                d01 = (a0m.y | l0m.y) ? 0.f : d01 * dscale;
                d10 = (a1m.x | l1m.x) ? 0.f : d10 * dscale;
                d11 = (a1m.y | l1m.y) ? 0.f : d11 * dscale;

                float p00 = (a0m.x ? 0.f : e00 * inv0) - d00;
                float p01 = (a0m.y ? 0.f : e01 * inv0) - d01;
                float p10 = (a1m.x ? 0.f : e10 * inv1) - d10;
                float p11 = (a1m.y ? 0.f : e11 * inv1) - d11;

                uint32_t h0, h1, l0, l1;
                PACKBF2(h0, p00, p01);
                PACKBF2(h1, p10, p11);
                float q00 = p00 - __uint_as_float(h0 << 16);
                float q01 = p01 - __uint_as_float(h0 & 0xffff0000u);
                float q10 = p10 - __uint_as_float(h1 << 16);
                float q11 = p11 - __uint_as_float(h1 & 0xffff0000u);
                PACKBF2(l0, q00, q01);
                PACKBF2(l1, q10, q11);
                if (jj == 0) { HA0 = h0; HA1 = h1; LA0 = l0; LA1 = l1; }
                else         { HB0 = h0; HB1 = h1; LB0 = l0; LB1 = l1; }
            }

            const uint4* gvk = gvt + ks * 16 * 32;
            #pragma unroll
            for (int jn = 0; jn < 16; jn++) {
                uint4 u = __ldg(gvk + jn * 32);
                mma16816(acc[jn][0], acc[jn][1], acc[jn][2], acc[jn][3],
                         HA0, HA1, HB0, HB1, u.x, u.z);
                mma16816(acc[jn][0], acc[jn][1], acc[jn][2], acc[jn][3],
                         HA0, HA1, HB0, HB1, u.y, u.w);
                mma16816(acc[jn][0], acc[jn][1], acc[jn][2], acc[jn][3],
                         LA0, LA1, LB0, LB1, u.x, u.z);
            }
        }
    }

    float* o0 = out + r0g * Fd + tig * 2;
    float* o1 = out + r1g * Fd + tig * 2;
    #pragma unroll
    for (int jn = 0; jn < 16; jn++) {
        *(float2*)(o0 + jn * 8) = make_float2(acc[jn][0], acc[jn][1]);
        *(float2*)(o1 + jn * 8) = make_float2(acc[jn][2], acc[jn][3]);
    }
}

extern "C" void kernel_launch(void* const* d_in, const int* in_sizes, int n_in,
                              void* d_out, int out_size) {
    const float* q   = (const float*)d_in[0];
    const float* k   = (const float*)d_in[1];
    const float* v   = (const float*)d_in[2];
    const float* cq  = (const float*)d_in[3];
    const float* ck  = (const float*)d_in[4];
    const int* am    = (const int*)d_in[5];
    const int* alm   = (const int*)d_in[6];
    const float* bs  = (const float*)d_in[7];
    const float* rm  = (const float*)d_in[8];
    float* out = (float*)d_out;

    cudaFuncSetAttribute(lsum_kernel,
                         cudaFuncAttributeMaxDynamicSharedMemorySize, SMEM1_BYTES);

    dim3 gridv(32, Bb);
    vprep_kernel<<<gridv, NT>>>(v);
    dim3 grid(Qd / 128, Bb);
    lsum_kernel<<<grid, NT, SMEM1_BYTES>>>(q, k);
    alibi_main_kernel<<<grid, NT>>>(cq, ck, am, alm, bs, rm, out);
}

// round 16
// speedup vs baseline: 1.3662x; 1.3662x over previous
#include <cuda_runtime.h>
#include <cuda_bf16.h>
#include <cuda_fp16.h>
#include <stdint.h>

#define Bb 16
#define Qd 2048
#define Kd 2048
#define Fd 128
#define KT 64
#define NT 256

// kernel1 smem (words): QS[128][68] + KS[64][68]
#define SMEM1_BYTES ((128*68 + 64*68)*4)
// kernel2 smem: 2 x 2048 uint4 (V fragment tiles)
#define SMEM2_BYTES (2*2048*16)

#define PACKBF2(r, lo, hi) asm("cvt.rn.bf16x2.f32 %0, %1, %2;" : "=r"(r) : "f"(hi), "f"(lo))
#define EX2(d, x) asm("ex2.approx.f32 %0, %1;" : "=f"(d) : "f"(x))
#define SQRTA(d, x) asm("sqrt.approx.f32 %0, %1;" : "=f"(d) : "f"(x))

#define CPASYNC16(sa, ga) asm volatile("cp.async.cg.shared.global [%0], [%1], 16;" :: "r"(sa), "l"(ga) : "memory")
#define CPCOMMIT() asm volatile("cp.async.commit_group;" ::: "memory")
#define CPWAIT(n) asm volatile("cp.async.wait_group %0;" :: "n"(n) : "memory")

__device__ float  g_lsum[Bb * Qd];
__device__ __half g_E[(size_t)256 * 32 * 8192];      // [cta][tile][warp][lane*32 + ..]
__device__ uint4  g_V[(size_t)Bb * 32 * 64 * 32];    // [b][tile][blk=ks*16+jn][lane]

__device__ __forceinline__ void mma16816(float& c0, float& c1, float& c2, float& c3,
                                         uint32_t a0, uint32_t a1, uint32_t a2, uint32_t a3,
                                         uint32_t b0, uint32_t b1) {
    asm volatile("mma.sync.aligned.m16n8k16.row.col.f32.bf16.bf16.f32 "
        "{%0,%1,%2,%3}, {%4,%5,%6,%7}, {%8,%9}, {%0,%1,%2,%3};"
        : "+f"(c0), "+f"(c1), "+f"(c2), "+f"(c3)
        : "r"(a0), "r"(a1), "r"(a2), "r"(a3), "r"(b0), "r"(b1));
}

#define LDSM4(d0, d1, d2, d3, addr) \
    asm volatile("ldmatrix.sync.aligned.m8n8.x4.shared.b16 {%0,%1,%2,%3}, [%4];" \
        : "=r"(d0), "=r"(d1), "=r"(d2), "=r"(d3) : "r"(addr))

extern __shared__ uint32_t smw[];

// ---------------- kernel 0: V -> hi/lo bf16 fragment-order scratch ----------------
__global__ void __launch_bounds__(NT, 2) vprep_kernel(const float* __restrict__ v)
{
    const int t = blockIdx.x, b = blockIdx.y;
    const int tid = threadIdx.x;
    const float* vp = v + ((size_t)b * Kd + t * KT) * Fd;
    uint4* gvt = g_V + ((size_t)(b * 32 + t)) * 2048;

    #pragma unroll
    for (int it = 0; it < 8; it++) {
        int idx = tid + it * NT;            // 0..2047
        int blk = idx >> 5, lane = idx & 31;
        int gid = lane >> 2, tig = lane & 3;
        int row = (blk >> 4) * 16 + tig * 2;
        int col = (blk & 15) * 8 + gid;
        float f0 = vp[row * Fd + col];
        float f1 = vp[(row + 1) * Fd + col];
        float f2 = vp[(row + 8) * Fd + col];
        float f3 = vp[(row + 9) * Fd + col];
        uint32_t pha, phb, pla, plb;
        PACKBF2(pha, f0, f1);
        PACKBF2(phb, f2, f3);
        float r0 = f0 - __uint_as_float(pha << 16);
        float r1 = f1 - __uint_as_float(pha & 0xffff0000u);
        PACKBF2(pla, r0, r1);
        float r2 = f2 - __uint_as_float(phb << 16);
        float r3 = f3 - __uint_as_float(phb & 0xffff0000u);
        PACKBF2(plb, r2, r3);
        gvt[idx] = make_uint4(pha, pla, phb, plb);
    }
}

// ---------------- kernel 1: S = QK^T, E = exp(s/sqrt(128) - 2) -> g_E, row sums -> g_lsum ----------------
__global__ void __launch_bounds__(NT, 1) lsum_kernel(
    const float* __restrict__ q, const float* __restrict__ k)
{
    const int b = blockIdx.y, q0 = blockIdx.x * 128;
    const int cid = b * 16 + blockIdx.x;
    const int tid = threadIdx.x;
    const int wid = tid >> 5, lane = tid & 31;
    const int gid = lane >> 2, tig = lane & 3;

    uint32_t* QS = smw;
    uint32_t* KS = smw + 128 * 68;

    const float C1 = 0.12753859788f;    // log2(e)/sqrt(128)
    const float C0 = -2.88539008178f;   // -2*log2(e)

    {
        const float* qp = q + ((size_t)b * Qd + q0) * Fd;
        #pragma unroll
        for (int it = 0; it < 16; it++) {
            int widx = tid + it * 256;
            int row = widx >> 5, w4 = widx & 31;
            float4 t = *(const float4*)(qp + row * Fd + 4 * w4);
            uint32_t p0, p1;
            PACKBF2(p0, t.x, t.y);
            PACKBF2(p1, t.z, t.w);
            *(uint2*)(QS + row * 68 + 2 * w4) = make_uint2(p0, p1);
        }
    }

    const int lm = lane >> 3, lr = lane & 7;
    const uint32_t qsb = (uint32_t)__cvta_generic_to_shared(QS);
    const uint32_t ksb = (uint32_t)__cvta_generic_to_shared(KS);
    const uint32_t aAddr0 = qsb + (((wid * 16 + ((lm & 1) << 3) + lr) * 68) + ((lm >> 1) << 2)) * 4;
    const uint32_t bAddr0 = ksb + (((((lm >> 1) << 3) + lr) * 68) + ((lm & 1) << 2)) * 4;

    float lsum0 = 0.f, lsum1 = 0.f;

    for (int t = 0; t < 32; t++) {
        const int k0 = t * KT;
        {
            const float* kp = k + ((size_t)b * Kd + k0) * Fd;
            #pragma unroll
            for (int it = 0; it < 8; it++) {
                int widx = tid + it * 256;
                int row = widx >> 5, w4 = widx & 31;
                float4 tt = *(const float4*)(kp + row * Fd + 4 * w4);
                uint32_t p0, p1;
                PACKBF2(p0, tt.x, tt.y);
                PACKBF2(p1, tt.z, tt.w);
                *(uint2*)(KS + row * 68 + 2 * w4) = make_uint2(p0, p1);
            }
        }
        __syncthreads();

        float sc[8][4];
        #pragma unroll
        for (int j = 0; j < 8; j++)
            #pragma unroll
            for (int c = 0; c < 4; c++) sc[j][c] = 0.f;

        #pragma unroll
        for (int ks = 0; ks < 8; ks++) {
            uint32_t a0, a1, a2, a3;
            LDSM4(a0, a1, a2, a3, aAddr0 + ks * 32);
            #pragma unroll
            for (int jp = 0; jp < 4; jp++) {
                uint32_t b0, b1, b2, b3;
                LDSM4(b0, b1, b2, b3, bAddr0 + jp * (16 * 68 * 4) + ks * 32);
                mma16816(sc[2*jp][0], sc[2*jp][1], sc[2*jp][2], sc[2*jp][3],
                         a0, a1, a2, a3, b0, b1);
                mma16816(sc[2*jp+1][0], sc[2*jp+1][1], sc[2*jp+1][2], sc[2*jp+1][3],
                         a0, a1, a2, a3, b2, b3);
            }
        }

        uint32_t Ebuf[16];
        #pragma unroll
        for (int j = 0; j < 8; j++) {
            float e0, e1, e2, e3;
            EX2(e0, fmaf(sc[j][0], C1, C0));
            EX2(e1, fmaf(sc[j][1], C1, C0));
            EX2(e2, fmaf(sc[j][2], C1, C0));
            EX2(e3, fmaf(sc[j][3], C1, C0));
            lsum0 += e0 + e1;
            lsum1 += e2 + e3;
            __half2 hA = __floats2half2_rn(e0, e1);
            __half2 hB = __floats2half2_rn(e2, e3);
            Ebuf[2*j]   = *(uint32_t*)&hA;
            Ebuf[2*j+1] = *(uint32_t*)&hB;
        }
        {
            const size_t eb = (((size_t)cid * 32 + t) * 8 + wid) * 1024 + lane * 32;
            uint4* ep = (uint4*)&g_E[eb];
            const uint4* sp = (const uint4*)Ebuf;
            ep[0] = sp[0]; ep[1] = sp[1]; ep[2] = sp[2]; ep[3] = sp[3];
        }
        __syncthreads();
    }

    lsum0 += __shfl_xor_sync(0xffffffffu, lsum0, 1);
    lsum0 += __shfl_xor_sync(0xffffffffu, lsum0, 2);
    lsum1 += __shfl_xor_sync(0xffffffffu, lsum1, 1);
    lsum1 += __shfl_xor_sync(0xffffffffu, lsum1, 2);
    if (tig == 0) {
        g_lsum[(size_t)b * Qd + q0 + wid * 16 + gid] = lsum0;
        g_lsum[(size_t)b * Qd + q0 + wid * 16 + gid + 8] = lsum1;
    }
}

// ---------------- kernel 2: P = (am?0:E*inv) - (or?0:dist), O = P @ V ----------------
__global__ void __launch_bounds__(NT, 2) alibi_main_kernel(
    const float* __restrict__ cq, const float* __restrict__ ck,
    const int* __restrict__ am, const int* __restrict__ alm,
    const float* __restrict__ bias_scale, const float* __restrict__ running_mean,
    float* __restrict__ out)
{
    const int b = blockIdx.y, q0 = blockIdx.x * 128;
    const int cid = b * 16 + blockIdx.x;
    const int tid = threadIdx.x;
    const int wid = tid >> 5, lane = tid & 31;
    const int gid = lane >> 2, tig = lane & 3;

    const uint32_t vi_sa = (uint32_t)__cvta_generic_to_shared(smw);

    const float dscale = bias_scale[0] / running_mean[0];

    const int r0l = wid * 16 + gid;
    const size_t r0g = (size_t)b * Qd + q0 + r0l;
    const size_t r1g = r0g + 8;
    const float cqx0 = cq[2 * r0g], cqy0 = cq[2 * r0g + 1];
    const float cqx1 = cq[2 * r1g], cqy1 = cq[2 * r1g + 1];
    const size_t m0 = r0g * (size_t)Kd, m1 = r1g * (size_t)Kd;
    const float inv0 = 1.f / g_lsum[r0g];
    const float inv1 = 1.f / g_lsum[r1g];

    float acc[16][4];
    #pragma unroll
    for (int jn = 0; jn < 16; jn++)
        #pragma unroll
        for (int c = 0; c < 4; c++) acc[jn][c] = 0.f;

    const uint4* gvb = g_V + (size_t)b * 32 * 2048;

    // prologue: prefetch tile 0 V into buffer 0
    {
        const uint4* gvt = gvb;
        uint32_t sbase = vi_sa;
        #pragma unroll
        for (int it = 0; it < 8; it++) {
            int idx = tid + it * NT;
            CPASYNC16(sbase + idx * 16, gvt + idx);
        }
        CPCOMMIT();
    }

    for (int t = 0; t < 32; t++) {
        const int k0 = t * KT;
        const int buf = t & 1;

        // prefetch t+1 into other buffer
        if (t < 31) {
            const uint4* gvt = gvb + (size_t)(t + 1) * 2048;
            uint32_t sbase = vi_sa + (buf ^ 1) * 32768;
            #pragma unroll
            for (int it = 0; it < 8; it++) {
                int idx = tid + it * NT;
                CPASYNC16(sbase + idx * 16, gvt + idx);
            }
            CPCOMMIT();
            CPWAIT(1);
        } else {
            CPWAIT(0);
        }
        __syncthreads();

        // E fragments: 4 x LDG.128
        uint32_t Er[16];
        {
            const size_t eb = (((size_t)cid * 32 + t) * 8 + wid) * 1024 + lane * 32;
            const uint4* ep = (const uint4*)&g_E[eb];
            uint4* dp = (uint4*)Er;
            dp[0] = ep[0]; dp[1] = ep[1]; dp[2] = ep[2]; dp[3] = ep[3];
        }

        const uint4* vbuf = (const uint4*)smw + buf * 2048 + lane;

        #pragma unroll
        for (int ks = 0; ks < 4; ks++) {
            uint32_t HA0, HA1, HB0, HB1, LA0, LA1, LB0, LB1;
            #pragma unroll
            for (int jj = 0; jj < 2; jj++) {
                int j = 2 * ks + jj;
                int c0 = k0 + j * 8 + tig * 2;
                float4 ckv = *(const float4*)(ck + ((size_t)b * Kd + c0) * 2);
                int2 a0m = *(const int2*)(am  + m0 + c0);
                int2 a1m = *(const int2*)(am  + m1 + c0);
                int2 l0m = *(const int2*)(alm + m0 + c0);
                int2 l1m = *(const int2*)(alm + m1 + c0);

                float2 fA = __half22float2(*(__half2*)&Er[2*j]);
                float2 fB = __half22float2(*(__half2*)&Er[2*j+1]);
                float e00 = fA.x, e01 = fA.y, e10 = fB.x, e11 = fB.y;

                float dxa = cqx0 - ckv.x, dya = cqy0 - ckv.y;
                float dxb = cqx0 - ckv.z, dyb = cqy0 - ckv.w;
                float dxc = cqx1 - ckv.x, dyc = cqy1 - ckv.y;
                float dxd = cqx1 - ckv.z, dyd = cqy1 - ckv.w;
                float d00, d01, d10, d11;
                SQRTA(d00, fmaf(dxa, dxa, dya * dya));
                SQRTA(d01, fmaf(dxb, dxb, dyb * dyb));
                SQRTA(d10, fmaf(dxc, dxc, dyc * dyc));
                SQRTA(d11, fmaf(dxd, dxd, dyd * dyd));

                d00 = (a0m.x | l0m.x) ? 0.f : d00 * dscale;
                d01 = (a0m.y | l0m.y) ? 0.f : d01 * dscale;
                d10 = (a1m.x | l1m.x) ? 0.f : d10 * dscale;
                d11 = (a1m.y | l1m.y) ? 0.f : d11 * dscale;

                float p00 = (a0m.x ? 0.f : e00 * inv0) - d00;
                float p01 = (a0m.y ? 0.f : e01 * inv0) - d01;
                float p10 = (a1m.x ? 0.f : e10 * inv1) - d10;
                float p11 = (a1m.y ? 0.f : e11 * inv1) - d11;

                uint32_t h0, h1, l0, l1;
                PACKBF2(h0, p00, p01);
                PACKBF2(h1, p10, p11);
                float q00 = p00 - __uint_as_float(h0 << 16);
                float q01 = p01 - __uint_as_float(h0 & 0xffff0000u);
                float q10 = p10 - __uint_as_float(h1 << 16);
                float q11 = p11 - __uint_as_float(h1 & 0xffff0000u);
                PACKBF2(l0, q00, q01);
                PACKBF2(l1, q10, q11);
                if (jj == 0) { HA0 = h0; HA1 = h1; LA0 = l0; LA1 = l1; }
                else         { HB0 = h0; HB1 = h1; LB0 = l0; LB1 = l1; }
            }

            const uint4* vk = vbuf + ks * 16 * 32;
            #pragma unroll
            for (int jn = 0; jn < 16; jn++) {
                uint4 u = vk[jn * 32];
                mma16816(acc[jn][0], acc[jn][1], acc[jn][2], acc[jn][3],
                         HA0, HA1, HB0, HB1, u.x, u.z);
                mma16816(acc[jn][0], acc[jn][1], acc[jn][2], acc[jn][3],
                         HA0, HA1, HB0, HB1, u.y, u.w);
                mma16816(acc[jn][0], acc[jn][1], acc[jn][2], acc[jn][3],
                         LA0, LA1, LB0, LB1, u.x, u.z);
            }
        }
        __syncthreads();
    }

    float* o0 = out + r0g * Fd + tig * 2;
    float* o1 = out + r1g * Fd + tig * 2;
    #pragma unroll
    for (int jn = 0; jn < 16; jn++) {
        *(float2*)(o0 + jn * 8) = make_float2(acc[jn][0], acc[jn][1]);
        *(float2*)(o1 + jn * 8) = make_float2(acc[jn][2], acc[jn][3]);
    }
}

extern "C" void kernel_launch(void* const* d_in, const int* in_sizes, int n_in,
                              void* d_out, int out_size) {
    const float* q   = (const float*)d_in[0];
    const float* k   = (const float*)d_in[1];
    const float* v   = (const float*)d_in[2];
    const float* cq  = (const float*)d_in[3];
    const float* ck  = (const float*)d_in[4];
    const int* am    = (const int*)d_in[5];
    const int* alm   = (const int*)d_in[6];
    const float* bs  = (const float*)d_in[7];
    const float* rm  = (const float*)d_in[8];
    float* out = (float*)d_out;

    cudaFuncSetAttribute(lsum_kernel,
                         cudaFuncAttributeMaxDynamicSharedMemorySize, SMEM1_BYTES);
    cudaFuncSetAttribute(alibi_main_kernel,
                         cudaFuncAttributeMaxDynamicSharedMemorySize, SMEM2_BYTES);

    dim3 gridv(32, Bb);
    vprep_kernel<<<gridv, NT>>>(v);
    dim3 grid(Qd / 128, Bb);
    lsum_kernel<<<grid, NT, SMEM1_BYTES>>>(q, k);
    alibi_main_kernel<<<grid, NT, SMEM2_BYTES>>>(cq, ck, am, alm, bs, rm, out);
}

// round 17
// speedup vs baseline: 1.4154x; 1.0360x over previous
#include <cuda_runtime.h>
#include <cuda_bf16.h>
#include <cuda_fp16.h>
#include <stdint.h>

#define Bb 16
#define Qd 2048
#define Kd 2048
#define Fd 128
#define KT 64
#define NT 256

// kernel1 smem (words): QS[128][68] + 2 x KS[64][68]
#define KSTRIDE_W 4352
#define SMEM1_BYTES ((128*68 + 2*KSTRIDE_W)*4)
// kernel2 smem: 2 x 2048 uint4 (V fragment tiles)
#define SMEM2_BYTES (2*2048*16)

#define PACKBF2(r, lo, hi) asm("cvt.rn.bf16x2.f32 %0, %1, %2;" : "=r"(r) : "f"(hi), "f"(lo))
#define EX2(d, x) asm("ex2.approx.f32 %0, %1;" : "=f"(d) : "f"(x))
#define SQRTA(d, x) asm("sqrt.approx.f32 %0, %1;" : "=f"(d) : "f"(x))

#define CPASYNC16(sa, ga) asm volatile("cp.async.cg.shared.global [%0], [%1], 16;" :: "r"(sa), "l"(ga) : "memory")
#define CPCOMMIT() asm volatile("cp.async.commit_group;" ::: "memory")
#define CPWAIT(n) asm volatile("cp.async.wait_group %0;" :: "n"(n) : "memory")

__device__ float  g_lsum[Bb * Qd];
__device__ __half g_E[(size_t)256 * 32 * 8192];      // [cta][tile][warp][lane*32 + ..]
__device__ uint4  g_V[(size_t)Bb * 32 * 64 * 32];    // [b][tile][blk=ks*16+jn][lane]
__device__ uint2  g_K[(size_t)Bb * 32 * 2048];       // [b][tile][row*32 + w2] bf16 pairs

__device__ __forceinline__ void mma16816(float& c0, float& c1, float& c2, float& c3,
                                         uint32_t a0, uint32_t a1, uint32_t a2, uint32_t a3,
                                         uint32_t b0, uint32_t b1) {
    asm volatile("mma.sync.aligned.m16n8k16.row.col.f32.bf16.bf16.f32 "
        "{%0,%1,%2,%3}, {%4,%5,%6,%7}, {%8,%9}, {%0,%1,%2,%3};"
        : "+f"(c0), "+f"(c1), "+f"(c2), "+f"(c3)
        : "r"(a0), "r"(a1), "r"(a2), "r"(a3), "r"(b0), "r"(b1));
}

#define LDSM4(d0, d1, d2, d3, addr) \
    asm volatile("ldmatrix.sync.aligned.m8n8.x4.shared.b16 {%0,%1,%2,%3}, [%4];" \
        : "=r"(d0), "=r"(d1), "=r"(d2), "=r"(d3) : "r"(addr))

extern __shared__ uint32_t smw[];

// ---------------- kernel 0: V -> hi/lo bf16 fragments; K -> bf16 rows ----------------
__global__ void __launch_bounds__(NT, 2) prep_kernel(
    const float* __restrict__ v, const float* __restrict__ k)
{
    const int t = blockIdx.x, b = blockIdx.y;
    const int tid = threadIdx.x;

    // V fragments
    {
        const float* vp = v + ((size_t)b * Kd + t * KT) * Fd;
        uint4* gvt = g_V + ((size_t)(b * 32 + t)) * 2048;
        #pragma unroll
        for (int it = 0; it < 8; it++) {
            int idx = tid + it * NT;            // 0..2047
            int blk = idx >> 5, lane = idx & 31;
            int gid = lane >> 2, tig = lane & 3;
            int row = (blk >> 4) * 16 + tig * 2;
            int col = (blk & 15) * 8 + gid;
            float f0 = vp[row * Fd + col];
            float f1 = vp[(row + 1) * Fd + col];
            float f2 = vp[(row + 8) * Fd + col];
            float f3 = vp[(row + 9) * Fd + col];
            uint32_t pha, phb, pla, plb;
            PACKBF2(pha, f0, f1);
            PACKBF2(phb, f2, f3);
            float r0 = f0 - __uint_as_float(pha << 16);
            float r1 = f1 - __uint_as_float(pha & 0xffff0000u);
            PACKBF2(pla, r0, r1);
            float r2 = f2 - __uint_as_float(phb << 16);
            float r3 = f3 - __uint_as_float(phb & 0xffff0000u);
            PACKBF2(plb, r2, r3);
            gvt[idx] = make_uint4(pha, pla, phb, plb);
        }
    }
    // K bf16 rows: [row][32 uint2], row stride 64 words
    {
        const float* kp = k + ((size_t)b * Kd + t * KT) * Fd;
        uint2* gkt = g_K + ((size_t)(b * 32 + t)) * 2048;
        #pragma unroll
        for (int it = 0; it < 8; it++) {
            int idx = tid + it * NT;            // 0..2047 = row*32 + w2
            int row = idx >> 5, w2 = idx & 31;
            float4 f = *(const float4*)(kp + row * Fd + 4 * w2);
            uint32_t p0, p1;
            PACKBF2(p0, f.x, f.y);
            PACKBF2(p1, f.z, f.w);
            gkt[idx] = make_uint2(p0, p1);
        }
    }
}

// ---------------- kernel 1: S = QK^T, E = exp(s/sqrt(128) - 2) -> g_E, row sums ----------------
__global__ void __launch_bounds__(NT, 2) lsum_kernel(
    const float* __restrict__ q)
{
    const int b = blockIdx.y, q0 = blockIdx.x * 128;
    const int cid = b * 16 + blockIdx.x;
    const int tid = threadIdx.x;
    const int wid = tid >> 5, lane = tid & 31;
    const int gid = lane >> 2, tig = lane & 3;

    uint32_t* QS = smw;
    const uint32_t qsb = (uint32_t)__cvta_generic_to_shared(QS);
    const uint32_t ksb = (uint32_t)__cvta_generic_to_shared(smw + 128 * 68);

    const float C1 = 0.12753859788f;    // log2(e)/sqrt(128)
    const float C0 = -2.88539008178f;   // -2*log2(e)

    {
        const float* qp = q + ((size_t)b * Qd + q0) * Fd;
        #pragma unroll
        for (int it = 0; it < 16; it++) {
            int widx = tid + it * 256;
            int row = widx >> 5, w4 = widx & 31;
            float4 t = *(const float4*)(qp + row * Fd + 4 * w4);
            uint32_t p0, p1;
            PACKBF2(p0, t.x, t.y);
            PACKBF2(p1, t.z, t.w);
            *(uint2*)(QS + row * 68 + 2 * w4) = make_uint2(p0, p1);
        }
    }

    const int lm = lane >> 3, lr = lane & 7;
    const uint32_t aAddr0 = qsb + (((wid * 16 + ((lm & 1) << 3) + lr) * 68) + ((lm >> 1) << 2)) * 4;
    const uint32_t bAddr0 = ksb + (((((lm >> 1) << 3) + lr) * 68) + ((lm & 1) << 2)) * 4;

    const uint4* gkb = (const uint4*)g_K + (size_t)b * 32 * 1024;

    float lsum0 = 0.f, lsum1 = 0.f;

    // prologue: prefetch K tile 0 into buffer 0
    {
        const uint4* gkt = gkb;
        #pragma unroll
        for (int it = 0; it < 4; it++) {
            int idx = tid + it * NT;            // 0..1023: row = idx>>4, w4 = idx&15
            int row = idx >> 4, w4 = idx & 15;
            CPASYNC16(ksb + (row * 68 + w4 * 4) * 4, gkt + idx);
        }
        CPCOMMIT();
    }

    for (int t = 0; t < 32; t++) {
        const int buf = t & 1;

        if (t < 31) {
            const uint4* gkt = gkb + (size_t)(t + 1) * 1024;
            uint32_t sbase = ksb + (buf ^ 1) * (KSTRIDE_W * 4);
            #pragma unroll
            for (int it = 0; it < 4; it++) {
                int idx = tid + it * NT;
                int row = idx >> 4, w4 = idx & 15;
                CPASYNC16(sbase + (row * 68 + w4 * 4) * 4, gkt + idx);
            }
            CPCOMMIT();
            CPWAIT(1);
        } else {
            CPWAIT(0);
        }
        __syncthreads();

        const uint32_t bA = bAddr0 + buf * (KSTRIDE_W * 4);

        float sc[8][4];
        #pragma unroll
        for (int j = 0; j < 8; j++)
            #pragma unroll
            for (int c = 0; c < 4; c++) sc[j][c] = 0.f;

        #pragma unroll
        for (int ks = 0; ks < 8; ks++) {
            uint32_t a0, a1, a2, a3;
            LDSM4(a0, a1, a2, a3, aAddr0 + ks * 32);
            #pragma unroll
            for (int jp = 0; jp < 4; jp++) {
                uint32_t b0, b1, b2, b3;
                LDSM4(b0, b1, b2, b3, bA + jp * (16 * 68 * 4) + ks * 32);
                mma16816(sc[2*jp][0], sc[2*jp][1], sc[2*jp][2], sc[2*jp][3],
                         a0, a1, a2, a3, b0, b1);
                mma16816(sc[2*jp+1][0], sc[2*jp+1][1], sc[2*jp+1][2], sc[2*jp+1][3],
                         a0, a1, a2, a3, b2, b3);
            }
        }

        uint32_t Ebuf[16];
        #pragma unroll
        for (int j = 0; j < 8; j++) {
            float e0, e1, e2, e3;
            EX2(e0, fmaf(sc[j][0], C1, C0));
            EX2(e1, fmaf(sc[j][1], C1, C0));
            EX2(e2, fmaf(sc[j][2], C1, C0));
            EX2(e3, fmaf(sc[j][3], C1, C0));
            lsum0 += e0 + e1;
            lsum1 += e2 + e3;
            __half2 hA = __floats2half2_rn(e0, e1);
            __half2 hB = __floats2half2_rn(e2, e3);
            Ebuf[2*j]   = *(uint32_t*)&hA;
            Ebuf[2*j+1] = *(uint32_t*)&hB;
        }
        {
            const size_t eb = (((size_t)cid * 32 + t) * 8 + wid) * 1024 + lane * 32;
            uint4* ep = (uint4*)&g_E[eb];
            const uint4* sp = (const uint4*)Ebuf;
            ep[0] = sp[0]; ep[1] = sp[1]; ep[2] = sp[2]; ep[3] = sp[3];
        }
        __syncthreads();
    }

    lsum0 += __shfl_xor_sync(0xffffffffu, lsum0, 1);
    lsum0 += __shfl_xor_sync(0xffffffffu, lsum0, 2);
    lsum1 += __shfl_xor_sync(0xffffffffu, lsum1, 1);
    lsum1 += __shfl_xor_sync(0xffffffffu, lsum1, 2);
    if (tig == 0) {
        g_lsum[(size_t)b * Qd + q0 + wid * 16 + gid] = lsum0;
        g_lsum[(size_t)b * Qd + q0 + wid * 16 + gid + 8] = lsum1;
    }
}

// ---------------- kernel 2: P = (am?0:E*inv) - (or?0:dist), O = P @ V ----------------
__global__ void __launch_bounds__(NT, 2) alibi_main_kernel(
    const float* __restrict__ cq, const float* __restrict__ ck,
    const int* __restrict__ am, const int* __restrict__ alm,
    const float* __restrict__ bias_scale, const float* __restrict__ running_mean,
    float* __restrict__ out)
{
    const int b = blockIdx.y, q0 = blockIdx.x * 128;
    const int cid = b * 16 + blockIdx.x;
    const int tid = threadIdx.x;
    const int wid = tid >> 5, lane = tid & 31;
    const int gid = lane >> 2, tig = lane & 3;

    const uint32_t vi_sa = (uint32_t)__cvta_generic_to_shared(smw);

    const float dscale = bias_scale[0] / running_mean[0];

    const int r0l = wid * 16 + gid;
    const size_t r0g = (size_t)b * Qd + q0 + r0l;
    const size_t r1g = r0g + 8;
    const float cqx0 = cq[2 * r0g], cqy0 = cq[2 * r0g + 1];
    const float cqx1 = cq[2 * r1g], cqy1 = cq[2 * r1g + 1];
    const size_t m0 = r0g * (size_t)Kd, m1 = r1g * (size_t)Kd;
    const float inv0 = 1.f / g_lsum[r0g];
    const float inv1 = 1.f / g_lsum[r1g];

    float acc[16][4];
    #pragma unroll
    for (int jn = 0; jn < 16; jn++)
        #pragma unroll
        for (int c = 0; c < 4; c++) acc[jn][c] = 0.f;

    const uint4* gvb = g_V + (size_t)b * 32 * 2048;

    {
        const uint4* gvt = gvb;
        #pragma unroll
        for (int it = 0; it < 8; it++) {
            int idx = tid + it * NT;
            CPASYNC16(vi_sa + idx * 16, gvt + idx);
        }
        CPCOMMIT();
    }

    for (int t = 0; t < 32; t++) {
        const int k0 = t * KT;
        const int buf = t & 1;

        if (t < 31) {
            const uint4* gvt = gvb + (size_t)(t + 1) * 2048;
            uint32_t sbase = vi_sa + (buf ^ 1) * 32768;
            #pragma unroll
            for (int it = 0; it < 8; it++) {
                int idx = tid + it * NT;
                CPASYNC16(sbase + idx * 16, gvt + idx);
            }
            CPCOMMIT();
            CPWAIT(1);
        } else {
            CPWAIT(0);
        }
        __syncthreads();

        uint32_t Er[16];
        {
            const size_t eb = (((size_t)cid * 32 + t) * 8 + wid) * 1024 + lane * 32;
            const uint4* ep = (const uint4*)&g_E[eb];
            uint4* dp = (uint4*)Er;
            dp[0] = ep[0]; dp[1] = ep[1]; dp[2] = ep[2]; dp[3] = ep[3];
        }

        const uint4* vbuf = (const uint4*)smw + buf * 2048 + lane;

        #pragma unroll
        for (int ks = 0; ks < 4; ks++) {
            uint32_t HA0, HA1, HB0, HB1, LA0, LA1, LB0, LB1;
            #pragma unroll
            for (int jj = 0; jj < 2; jj++) {
                int j = 2 * ks + jj;
                int c0 = k0 + j * 8 + tig * 2;
                float4 ckv = *(const float4*)(ck + ((size_t)b * Kd + c0) * 2);
                int2 a0m = *(const int2*)(am  + m0 + c0);
                int2 a1m = *(const int2*)(am  + m1 + c0);
                int2 l0m = *(const int2*)(alm + m0 + c0);
                int2 l1m = *(const int2*)(alm + m1 + c0);

                float2 fA = __half22float2(*(__half2*)&Er[2*j]);
                float2 fB = __half22float2(*(__half2*)&Er[2*j+1]);
                float e00 = fA.x, e01 = fA.y, e10 = fB.x, e11 = fB.y;

                float dxa = cqx0 - ckv.x, dya = cqy0 - ckv.y;
                float dxb = cqx0 - ckv.z, dyb = cqy0 - ckv.w;
                float dxc = cqx1 - ckv.x, dyc = cqy1 - ckv.y;
                float dxd = cqx1 - ckv.z, dyd = cqy1 - ckv.w;
                float d00, d01, d10, d11;
                SQRTA(d00, fmaf(dxa, dxa, dya * dya));
                SQRTA(d01, fmaf(dxb, dxb, dyb * dyb));
                SQRTA(d10, fmaf(dxc, dxc, dyc * dyc));
                SQRTA(d11, fmaf(dxd, dxd, dyd * dyd));

                d00 = (a0m.x | l0m.x) ? 0.f : d00 * dscale;
                d01 = (a0m.y | l0m.y) ? 0.f : d01 * dscale;
                d10 = (a1m.x | l1m.x) ? 0.f : d10 * dscale;
                d11 = (a1m.y | l1m.y) ? 0.f : d11 * dscale;

                float p00 = (a0m.x ? 0.f : e00 * inv0) - d00;
                float p01 = (a0m.y ? 0.f : e01 * inv0) - d01;
                float p10 = (a1m.x ? 0.f : e10 * inv1) - d10;
                float p11 = (a1m.y ? 0.f : e11 * inv1) - d11;

                uint32_t h0, h1, l0, l1;
                PACKBF2(h0, p00, p01);
                PACKBF2(h1, p10, p11);
                float q00 = p00 - __uint_as_float(h0 << 16);
                float q01 = p01 - __uint_as_float(h0 & 0xffff0000u);
                float q10 = p10 - __uint_as_float(h1 << 16);
                float q11 = p11 - __uint_as_float(h1 & 0xffff0000u);
                PACKBF2(l0, q00, q01);
                PACKBF2(l1, q10, q11);
                if (jj == 0) { HA0 = h0; HA1 = h1; LA0 = l0; LA1 = l1; }
                else         { HB0 = h0; HB1 = h1; LB0 = l0; LB1 = l1; }
            }

            const uint4* vk = vbuf + ks * 16 * 32;
            #pragma unroll
            for (int jn = 0; jn < 16; jn++) {
                uint4 u = vk[jn * 32];
                mma16816(acc[jn][0], acc[jn][1], acc[jn][2], acc[jn][3],
                         HA0, HA1, HB0, HB1, u.x, u.z);
                mma16816(acc[jn][0], acc[jn][1], acc[jn][2], acc[jn][3],
                         HA0, HA1, HB0, HB1, u.y, u.w);
                mma16816(acc[jn][0], acc[jn][1], acc[jn][2], acc[jn][3],
                         LA0, LA1, LB0, LB1, u.x, u.z);
            }
        }
        __syncthreads();
    }

    float* o0 = out + r0g * Fd + tig * 2;
    float* o1 = out + r1g * Fd + tig * 2;
    #pragma unroll
    for (int jn = 0; jn < 16; jn++) {
        *(float2*)(o0 + jn * 8) = make_float2(acc[jn][0], acc[jn][1]);
        *(float2*)(o1 + jn * 8) = make_float2(acc[jn][2], acc[jn][3]);
    }
}

extern "C" void kernel_launch(void* const* d_in, const int* in_sizes, int n_in,
                              void* d_out, int out_size) {
    const float* q   = (const float*)d_in[0];
    const float* k   = (const float*)d_in[1];
    const float* v   = (const float*)d_in[2];
    const float* cq  = (const float*)d_in[3];
    const float* ck  = (const float*)d_in[4];
    const int* am    = (const int*)d_in[5];
    const int* alm   = (const int*)d_in[6];
    const float* bs  = (const float*)d_in[7];
    const float* rm  = (const float*)d_in[8];
    float* out = (float*)d_out;

    cudaFuncSetAttribute(lsum_kernel,
                         cudaFuncAttributeMaxDynamicSharedMemorySize, SMEM1_BYTES);
    cudaFuncSetAttribute(alibi_main_kernel,
                         cudaFuncAttributeMaxDynamicSharedMemorySize, SMEM2_BYTES);

    dim3 gridv(32, Bb);
    prep_kernel<<<gridv, NT>>>(v, k);
    dim3 grid(Qd / 128, Bb);
    lsum_kernel<<<grid, NT, SMEM1_BYTES>>>(q);
    alibi_main_kernel<<<grid, NT, SMEM2_BYTES>>>(cq, ck, am, alm, bs, rm, out);
}